// round 1
// baseline (speedup 1.0000x reference)
#include <cuda_runtime.h>

// L0 contraction: out[b, n] = cg_n * sum_{m in block n} sphc[b, m]^2
// Blocks (per row of 15): [0:3) deg1, [3:8) deg2, [8:15) deg3.
// Pure HBM-bound: 240MB read + 48MB write. Strategy: smem-staged tiles so
// all global traffic is aligned float4, compute per-row from smem
// (stride-15 reads and stride-3 writes are bank-conflict-free).

constexpr int THREADS = 128;
constexpr int ROWS_PER_BLOCK = 512;
constexpr int M = 15;

__global__ __launch_bounds__(THREADS) void l0_contraction_kernel(
    const float* __restrict__ sphc,
    const float* __restrict__ cg,
    float* __restrict__ out,
    int B)
{
    __shared__ float s_in[ROWS_PER_BLOCK * M];   // 30720 B
    __shared__ float s_out[ROWS_PER_BLOCK * 3];  // 6144 B

    const float c0 = __ldg(cg + 0);  // 1/sqrt(3)
    const float c1 = __ldg(cg + 3);  // 1/sqrt(5)
    const float c2 = __ldg(cg + 8);  // 1/sqrt(7)

    const long long row0 = (long long)blockIdx.x * ROWS_PER_BLOCK;
    const int tid = threadIdx.x;
    const int nrows = min((long long)ROWS_PER_BLOCK, (long long)B - row0);

    if (nrows == ROWS_PER_BLOCK) {
        // ---- full tile: fully vectorized path ----
        // 512 rows * 15 floats = 1920 float4; block-aligned (512*60B % 16 == 0)
        const float4* gin = reinterpret_cast<const float4*>(sphc + row0 * M);
        float4* s4 = reinterpret_cast<float4*>(s_in);
        #pragma unroll
        for (int i = 0; i < (ROWS_PER_BLOCK * M / 4) / THREADS; i++)  // 15 iters
            s4[tid + i * THREADS] = gin[tid + i * THREADS];
        __syncthreads();

        #pragma unroll
        for (int j = 0; j < ROWS_PER_BLOCK / THREADS; j++) {  // 4 rows/thread
            const int r = tid + j * THREADS;
            const float* x = s_in + r * M;
            float a = x[0]*x[0] + x[1]*x[1] + x[2]*x[2];
            float b = x[3]*x[3] + x[4]*x[4] + x[5]*x[5] + x[6]*x[6] + x[7]*x[7];
            float c = x[8]*x[8] + x[9]*x[9] + x[10]*x[10] + x[11]*x[11]
                    + x[12]*x[12] + x[13]*x[13] + x[14]*x[14];
            s_out[r * 3 + 0] = a * c0;
            s_out[r * 3 + 1] = b * c1;
            s_out[r * 3 + 2] = c * c2;
        }
        __syncthreads();

        // 512 rows * 3 floats = 384 float4
        float4* gout = reinterpret_cast<float4*>(out + row0 * 3);
        const float4* so4 = reinterpret_cast<const float4*>(s_out);
        #pragma unroll
        for (int i = 0; i < (ROWS_PER_BLOCK * 3 / 4) / THREADS; i++)  // 3 iters
            gout[tid + i * THREADS] = so4[tid + i * THREADS];
    } else {
        // ---- tail tile: scalar, guarded ----
        const float* gin = sphc + row0 * M;
        const int nf = nrows * M;
        for (int i = tid; i < nf; i += THREADS) s_in[i] = gin[i];
        __syncthreads();

        for (int r = tid; r < nrows; r += THREADS) {
            const float* x = s_in + r * M;
            float a = x[0]*x[0] + x[1]*x[1] + x[2]*x[2];
            float b = x[3]*x[3] + x[4]*x[4] + x[5]*x[5] + x[6]*x[6] + x[7]*x[7];
            float c = x[8]*x[8] + x[9]*x[9] + x[10]*x[10] + x[11]*x[11]
                    + x[12]*x[12] + x[13]*x[13] + x[14]*x[14];
            s_out[r * 3 + 0] = a * c0;
            s_out[r * 3 + 1] = b * c1;
            s_out[r * 3 + 2] = c * c2;
        }
        __syncthreads();

        float* gout = out + row0 * 3;
        const int no = nrows * 3;
        for (int i = tid; i < no; i += THREADS) gout[i] = s_out[i];
    }
}

extern "C" void kernel_launch(void* const* d_in, const int* in_sizes, int n_in,
                              void* d_out, int out_size) {
    const float* sphc = (const float*)d_in[0];
    const float* cg   = (const float*)d_in[1];
    // d_in[2] = segment_ids (structure is compile-time: 3/5/7 blocks)
    float* out = (float*)d_out;

    const int B = in_sizes[0] / M;  // 4,000,000
    const int grid = (B + ROWS_PER_BLOCK - 1) / ROWS_PER_BLOCK;
    l0_contraction_kernel<<<grid, THREADS>>>(sphc, cg, out, B);
}

// round 2
// speedup vs baseline: 1.0419x; 1.0419x over previous
#include <cuda_runtime.h>

// L0 contraction: out[b, n] = cg_n * sum_{m in block n} sphc[b, m]^2
// Row layout (15 floats): [0:3) deg1, [3:8) deg2, [8:15) deg3.
// HBM-bound: 240MB read + 48MB write, floor ~42us at ~7TB/s.
// R2 change: 256-row tiles (18KB smem) + __launch_bounds__(128,12)
//            -> 12 blocks/SM, 48 warps (75% occ) for DRAM MLP.

constexpr int THREADS = 128;
constexpr int ROWS_PER_BLOCK = 256;
constexpr int M = 15;

__global__ __launch_bounds__(THREADS, 12) void l0_contraction_kernel(
    const float* __restrict__ sphc,
    const float* __restrict__ cg,
    float* __restrict__ out,
    int B)
{
    __shared__ float s_in[ROWS_PER_BLOCK * M];   // 15360 B
    __shared__ float s_out[ROWS_PER_BLOCK * 3];  //  3072 B

    const float c0 = __ldg(cg + 0);  // 1/sqrt(3)
    const float c1 = __ldg(cg + 3);  // 1/sqrt(5)
    const float c2 = __ldg(cg + 8);  // 1/sqrt(7)

    const long long row0 = (long long)blockIdx.x * ROWS_PER_BLOCK;
    const int tid = threadIdx.x;
    const int nrows = min((long long)ROWS_PER_BLOCK, (long long)B - row0);

    if (nrows == ROWS_PER_BLOCK) {
        // ---- full tile ----
        // 256 rows * 15 floats = 960 float4 (256*60B is 16B-aligned per tile)
        const float4* gin = reinterpret_cast<const float4*>(sphc + row0 * M);
        float4* s4 = reinterpret_cast<float4*>(s_in);
        constexpr int NV = ROWS_PER_BLOCK * M / 4;  // 960
        #pragma unroll
        for (int i = 0; i < (NV + THREADS - 1) / THREADS; i++) {  // 8 iters
            const int idx = tid + i * THREADS;
            if (idx < NV) s4[idx] = gin[idx];
        }
        __syncthreads();

        #pragma unroll
        for (int j = 0; j < ROWS_PER_BLOCK / THREADS; j++) {  // 2 rows/thread
            const int r = tid + j * THREADS;
            const float* x = s_in + r * M;  // stride 15: conflict-free
            float a = x[0]*x[0] + x[1]*x[1] + x[2]*x[2];
            float b = x[3]*x[3] + x[4]*x[4] + x[5]*x[5] + x[6]*x[6] + x[7]*x[7];
            float c = x[8]*x[8] + x[9]*x[9] + x[10]*x[10] + x[11]*x[11]
                    + x[12]*x[12] + x[13]*x[13] + x[14]*x[14];
            s_out[r * 3 + 0] = a * c0;
            s_out[r * 3 + 1] = b * c1;
            s_out[r * 3 + 2] = c * c2;
        }
        __syncthreads();

        // 256 rows * 3 floats = 192 float4
        float4* gout = reinterpret_cast<float4*>(out + row0 * 3);
        const float4* so4 = reinterpret_cast<const float4*>(s_out);
        constexpr int NO = ROWS_PER_BLOCK * 3 / 4;  // 192
        #pragma unroll
        for (int i = 0; i < (NO + THREADS - 1) / THREADS; i++) {  // 2 iters
            const int idx = tid + i * THREADS;
            if (idx < NO) gout[idx] = so4[idx];
        }
    } else {
        // ---- tail tile: scalar, guarded ----
        const float* gin = sphc + row0 * M;
        const int nf = nrows * M;
        for (int i = tid; i < nf; i += THREADS) s_in[i] = gin[i];
        __syncthreads();

        for (int r = tid; r < nrows; r += THREADS) {
            const float* x = s_in + r * M;
            float a = x[0]*x[0] + x[1]*x[1] + x[2]*x[2];
            float b = x[3]*x[3] + x[4]*x[4] + x[5]*x[5] + x[6]*x[6] + x[7]*x[7];
            float c = x[8]*x[8] + x[9]*x[9] + x[10]*x[10] + x[11]*x[11]
                    + x[12]*x[12] + x[13]*x[13] + x[14]*x[14];
            s_out[r * 3 + 0] = a * c0;
            s_out[r * 3 + 1] = b * c1;
            s_out[r * 3 + 2] = c * c2;
        }
        __syncthreads();

        float* gout = out + row0 * 3;
        const int no = nrows * 3;
        for (int i = tid; i < no; i += THREADS) gout[i] = s_out[i];
    }
}

extern "C" void kernel_launch(void* const* d_in, const int* in_sizes, int n_in,
                              void* d_out, int out_size) {
    const float* sphc = (const float*)d_in[0];
    const float* cg   = (const float*)d_in[1];
    // d_in[2] = segment_ids (structure is compile-time: 3/5/7 blocks)
    float* out = (float*)d_out;

    const int B = in_sizes[0] / M;  // 4,000,000
    const int grid = (B + ROWS_PER_BLOCK - 1) / ROWS_PER_BLOCK;
    l0_contraction_kernel<<<grid, THREADS>>>(sphc, cg, out, B);
}

// round 3
// speedup vs baseline: 1.0503x; 1.0081x over previous
#include <cuda_runtime.h>
#include <cstdint>

// L0 contraction: out[b,n] = cg_n * sum_{m in deg-block n} sphc[b,m]^2
// Row of 15 floats: [0:3) deg1, [3:8) deg2, [8:15) deg3.
// R3: persistent blocks + 3-stage cp.async.bulk (UBLKCP) ring with mbarriers.
// Loads stream continuously through the async proxy; consumers read smem
// (stride-15 -> bank-conflict-free) and store 3 floats/row directly.

constexpr int THREADS    = 128;
constexpr int TILE_ROWS  = 256;
constexpr int M          = 15;
constexpr int STAGES     = 3;
constexpr int TILE_FLOATS = TILE_ROWS * M;        // 3840
constexpr int TILE_BYTES  = TILE_FLOATS * 4;      // 15360 (16B multiple)

#define MBAR_INIT(addr, cnt) \
    asm volatile("mbarrier.init.shared.b64 [%0], %1;" :: "r"(addr), "r"(cnt) : "memory")
#define MBAR_EXPECT_TX(addr, bytes) \
    asm volatile("mbarrier.arrive.expect_tx.shared.b64 _, [%0], %1;" :: "r"(addr), "r"(bytes) : "memory")
#define MBAR_ARRIVE(addr) \
    asm volatile("mbarrier.arrive.shared.b64 _, [%0];" :: "r"(addr) : "memory")
#define MBAR_WAIT(addr, ph) do {                                               \
    uint32_t _done;                                                            \
    asm volatile("{\n\t.reg .pred p;\n\t"                                      \
        "mbarrier.try_wait.parity.acquire.cta.shared::cta.b64 p, [%1], %2;\n\t"\
        "selp.b32 %0, 1, 0, p;\n\t}"                                           \
        : "=r"(_done) : "r"(addr), "r"(ph) : "memory");                        \
    while (!_done) {                                                           \
        asm volatile("{\n\t.reg .pred p;\n\t"                                  \
            "mbarrier.try_wait.parity.acquire.cta.shared::cta.b64 p, [%1], %2, 0x989680;\n\t" \
            "selp.b32 %0, 1, 0, p;\n\t}"                                       \
            : "=r"(_done) : "r"(addr), "r"(ph) : "memory");                    \
    }                                                                          \
} while (0)

__device__ __forceinline__ uint32_t smem_u32(const void* p) {
    uint32_t a;
    asm("{ .reg .u64 t; cvta.to.shared.u64 t, %1; cvt.u32.u64 %0, t; }" : "=r"(a) : "l"(p));
    return a;
}

__global__ __launch_bounds__(THREADS) void l0_pipe_kernel(
    const float* __restrict__ sphc,
    const float* __restrict__ cg,
    float* __restrict__ out,
    int ntiles, int B)
{
    __shared__ alignas(128) float s_in[STAGES][TILE_FLOATS];  // 46080 B
    __shared__ alignas(8) uint64_t mb_full[STAGES];
    __shared__ alignas(8) uint64_t mb_empty[STAGES];

    const int tid = threadIdx.x;
    uint32_t full_a[STAGES], empty_a[STAGES], sbuf_a[STAGES];
    #pragma unroll
    for (int s = 0; s < STAGES; s++) {
        full_a[s]  = smem_u32(&mb_full[s]);
        empty_a[s] = smem_u32(&mb_empty[s]);
        sbuf_a[s]  = smem_u32(&s_in[s][0]);
    }
    if (tid == 0) {
        #pragma unroll
        for (int s = 0; s < STAGES; s++) {
            MBAR_INIT(full_a[s], 1);        // completes via expect_tx + bulk bytes
            MBAR_INIT(empty_a[s], THREADS); // all threads arrive after consuming
        }
    }
    __syncthreads();

    const float c0 = __ldg(cg + 0);   // 1/sqrt(3)
    const float c1 = __ldg(cg + 3);   // 1/sqrt(5)
    const float c2 = __ldg(cg + 8);   // 1/sqrt(7)

    // Tail rows (B not multiple of TILE_ROWS): handled by block 0, direct.
    if (blockIdx.x == 0) {
        for (int r = ntiles * TILE_ROWS + tid; r < B; r += THREADS) {
            const float* x = sphc + (size_t)r * M;
            float a = x[0]*x[0] + x[1]*x[1] + x[2]*x[2];
            float b = x[3]*x[3] + x[4]*x[4] + x[5]*x[5] + x[6]*x[6] + x[7]*x[7];
            float c = x[8]*x[8] + x[9]*x[9] + x[10]*x[10] + x[11]*x[11]
                    + x[12]*x[12] + x[13]*x[13] + x[14]*x[14];
            out[r*3 + 0] = a * c0;
            out[r*3 + 1] = b * c1;
            out[r*3 + 2] = c * c2;
        }
    }

    // This block's tiles: grid-stride. fill f / consume i map to
    // tile = blockIdx.x + k * gridDim.x.
    const int nmine = (blockIdx.x < ntiles)
                    ? (ntiles - blockIdx.x + gridDim.x - 1) / gridDim.x : 0;
    if (nmine == 0) return;

    int p_stage = 0, p_phase = 1;   // producer: first empty-wait passes
    int c_stage = 0, c_phase = 0;   // consumer: waits first fill

    // Prologue: fill up to STAGES tiles.
    if (tid == 0) {
        const int npro = nmine < STAGES ? nmine : STAGES;
        for (int f = 0; f < npro; f++) {
            MBAR_WAIT(empty_a[p_stage], p_phase);
            MBAR_EXPECT_TX(full_a[p_stage], TILE_BYTES);
            const size_t tile = (size_t)blockIdx.x + (size_t)f * gridDim.x;
            const float* src = sphc + tile * TILE_FLOATS;
            asm volatile(
                "cp.async.bulk.shared::cta.global.mbarrier::complete_tx::bytes "
                "[%0], [%1], %2, [%3];"
                :: "r"(sbuf_a[p_stage]), "l"(src), "r"(TILE_BYTES), "r"(full_a[p_stage])
                : "memory");
            if (++p_stage == STAGES) { p_stage = 0; p_phase ^= 1; }
        }
    }

    for (int i = 0; i < nmine; i++) {
        MBAR_WAIT(full_a[c_stage], c_phase);

        const int tile = blockIdx.x + i * gridDim.x;
        const float* __restrict__ buf = s_in[c_stage];
        #pragma unroll
        for (int j = 0; j < TILE_ROWS / THREADS; j++) {   // 2 rows/thread
            const int r = tid + j * THREADS;
            const float* x = buf + r * M;     // stride 15: conflict-free
            float a = x[0]*x[0] + x[1]*x[1] + x[2]*x[2];
            float b = x[3]*x[3] + x[4]*x[4] + x[5]*x[5] + x[6]*x[6] + x[7]*x[7];
            float c = x[8]*x[8] + x[9]*x[9] + x[10]*x[10] + x[11]*x[11]
                    + x[12]*x[12] + x[13]*x[13] + x[14]*x[14];
            const size_t o = ((size_t)tile * TILE_ROWS + r) * 3;
            out[o + 0] = a * c0;
            out[o + 1] = b * c1;
            out[o + 2] = c * c2;
        }

        MBAR_ARRIVE(empty_a[c_stage]);
        if (++c_stage == STAGES) { c_stage = 0; c_phase ^= 1; }

        // Producer: refill the stage we just freed with tile i+STAGES.
        if (tid == 0) {
            const int f = i + STAGES;
            if (f < nmine) {
                MBAR_WAIT(empty_a[p_stage], p_phase);
                MBAR_EXPECT_TX(full_a[p_stage], TILE_BYTES);
                const size_t tile_f = (size_t)blockIdx.x + (size_t)f * gridDim.x;
                const float* src = sphc + tile_f * TILE_FLOATS;
                asm volatile(
                    "cp.async.bulk.shared::cta.global.mbarrier::complete_tx::bytes "
                    "[%0], [%1], %2, [%3];"
                    :: "r"(sbuf_a[p_stage]), "l"(src), "r"(TILE_BYTES), "r"(full_a[p_stage])
                    : "memory");
                if (++p_stage == STAGES) { p_stage = 0; p_phase ^= 1; }
            }
        }
    }
}

extern "C" void kernel_launch(void* const* d_in, const int* in_sizes, int n_in,
                              void* d_out, int out_size) {
    const float* sphc = (const float*)d_in[0];
    const float* cg   = (const float*)d_in[1];
    float* out = (float*)d_out;

    const int B = in_sizes[0] / M;               // 4,000,000
    const int ntiles = B / TILE_ROWS;            // 15625
    int grid = 152 * 4;                          // persistent: 4 blocks/SM
    if (grid > ntiles && ntiles > 0) grid = ntiles;
    if (ntiles == 0) grid = 1;                   // tail-only path
    l0_pipe_kernel<<<grid, THREADS>>>(sphc, cg, out, ntiles, B);
}

// round 4
// speedup vs baseline: 1.4023x; 1.3351x over previous
#include <cuda_runtime.h>

// L0 contraction: out[b,n] = cg_n * sum_{m in deg-block n} sphc[b,m]^2
// Row of 15 floats: [0:3) deg1, [3:8) deg2, [8:15) deg3.
// Traffic floor: 240MB read + 48MB write = 288MB.
// R4: 160-row tiles (11.5KB smem) x 128 thr -> 16 blocks/SM = 64 warps
//     (100% occupancy), streaming cache hints on the one-pass streams.

constexpr int THREADS = 128;
constexpr int ROWS_PER_BLOCK = 160;
constexpr int M = 15;
constexpr int NV = ROWS_PER_BLOCK * M / 4;   // 600 float4 in
constexpr int NO = ROWS_PER_BLOCK * 3 / 4;   // 120 float4 out

__global__ __launch_bounds__(THREADS, 16) void l0_contraction_kernel(
    const float* __restrict__ sphc,
    const float* __restrict__ cg,
    float* __restrict__ out,
    int B)
{
    __shared__ float s_in[ROWS_PER_BLOCK * M];   // 9600 B
    __shared__ float s_out[ROWS_PER_BLOCK * 3];  // 1920 B

    const float c0 = __ldg(cg + 0);  // 1/sqrt(3)
    const float c1 = __ldg(cg + 3);  // 1/sqrt(5)
    const float c2 = __ldg(cg + 8);  // 1/sqrt(7)

    const long long row0 = (long long)blockIdx.x * ROWS_PER_BLOCK;
    const int tid = threadIdx.x;
    const int nrows = (int)min((long long)ROWS_PER_BLOCK, (long long)B - row0);

    if (nrows == ROWS_PER_BLOCK) {
        // ---- full tile ----
        // 160 rows * 60B = 9600B per tile; tile base is 16B-aligned (9600%16==0).
        const float4* gin = reinterpret_cast<const float4*>(sphc + row0 * M);
        float4* s4 = reinterpret_cast<float4*>(s_in);
        #pragma unroll
        for (int i = 0; i < (NV + THREADS - 1) / THREADS; i++) {  // 5 iters
            const int idx = tid + i * THREADS;
            if (idx < NV) s4[idx] = __ldcs(gin + idx);  // evict-first stream
        }
        __syncthreads();

        // 160 rows over 128 threads: iter0 all lanes, iter1 lanes < 32.
        #pragma unroll
        for (int j = 0; j < 2; j++) {
            const int r = tid + j * THREADS;
            if (r < ROWS_PER_BLOCK) {
                const float* x = s_in + r * M;   // stride 15: conflict-free
                float a = x[0]*x[0] + x[1]*x[1] + x[2]*x[2];
                float b = x[3]*x[3] + x[4]*x[4] + x[5]*x[5] + x[6]*x[6] + x[7]*x[7];
                float c = x[8]*x[8] + x[9]*x[9] + x[10]*x[10] + x[11]*x[11]
                        + x[12]*x[12] + x[13]*x[13] + x[14]*x[14];
                s_out[r * 3 + 0] = a * c0;
                s_out[r * 3 + 1] = b * c1;
                s_out[r * 3 + 2] = c * c2;
            }
        }
        __syncthreads();

        float4* gout = reinterpret_cast<float4*>(out + row0 * 3);
        const float4* so4 = reinterpret_cast<const float4*>(s_out);
        if (tid < NO) __stcs(gout + tid, so4[tid]);   // 120 float4
    } else {
        // ---- tail tile: scalar, guarded ----
        const float* gin = sphc + row0 * M;
        const int nf = nrows * M;
        for (int i = tid; i < nf; i += THREADS) s_in[i] = gin[i];
        __syncthreads();

        for (int r = tid; r < nrows; r += THREADS) {
            const float* x = s_in + r * M;
            float a = x[0]*x[0] + x[1]*x[1] + x[2]*x[2];
            float b = x[3]*x[3] + x[4]*x[4] + x[5]*x[5] + x[6]*x[6] + x[7]*x[7];
            float c = x[8]*x[8] + x[9]*x[9] + x[10]*x[10] + x[11]*x[11]
                    + x[12]*x[12] + x[13]*x[13] + x[14]*x[14];
            s_out[r * 3 + 0] = a * c0;
            s_out[r * 3 + 1] = b * c1;
            s_out[r * 3 + 2] = c * c2;
        }
        __syncthreads();

        float* gout = out + row0 * 3;
        const int no = nrows * 3;
        for (int i = tid; i < no; i += THREADS) gout[i] = s_out[i];
    }
}

extern "C" void kernel_launch(void* const* d_in, const int* in_sizes, int n_in,
                              void* d_out, int out_size) {
    const float* sphc = (const float*)d_in[0];
    const float* cg   = (const float*)d_in[1];
    // d_in[2] = segment_ids (structure is compile-time: 3/5/7 blocks)
    float* out = (float*)d_out;

    const int B = in_sizes[0] / M;  // 4,000,000
    const int grid = (B + ROWS_PER_BLOCK - 1) / ROWS_PER_BLOCK;  // 25000
    l0_contraction_kernel<<<grid, THREADS>>>(sphc, cg, out, B);
}